// round 1
// baseline (speedup 1.0000x reference)
#include <cuda_runtime.h>

#define CL 4096
#define IL 1024
#define NE 512
#define HS 64
#define BATCHN 8

// scratch for projected q,k,v (fp32), 8 MB each
__device__ float g_q[BATCHN * CL * HS];
__device__ float g_k[BATCHN * CL * HS];
__device__ float g_v[BATCHN * CL * HS];

// ---------------------------------------------------------------------------
// Projection: out[64x64] tile = X[64x512] @ W[512x64]
// grid = (512 row-tiles, 3 matrices), block = 256 threads (16x16, 4x4 micro)
// ---------------------------------------------------------------------------
__global__ void proj_kernel(const float* __restrict__ x,
                            const float* __restrict__ Wq,
                            const float* __restrict__ Wk,
                            const float* __restrict__ Wv) {
    __shared__ __align__(16) float Xs[64][68];
    __shared__ __align__(16) float WsT[64][68];   // [col][k]

    const int mat = blockIdx.y;
    const float* W = (mat == 0) ? Wq : ((mat == 1) ? Wk : Wv);
    float* outp = (mat == 0) ? g_q : ((mat == 1) ? g_k : g_v);

    const int tid = threadIdx.x;
    const int ty = tid >> 4, tx = tid & 15;
    const int i0 = ty * 4, c0 = tx * 4;
    const int row0 = blockIdx.x * 64;

    float acc[4][4] = {};

    for (int k0 = 0; k0 < NE; k0 += 64) {
        for (int i = tid; i < 4096; i += 256) {
            int a = i >> 6, b = i & 63;
            Xs[a][b] = x[(size_t)(row0 + a) * NE + (k0 + b)];
            // WsT[c][kk] = W[(k0+kk)*HS + c]
            WsT[b][a] = W[(size_t)(k0 + a) * HS + b];
        }
        __syncthreads();
#pragma unroll
        for (int k4 = 0; k4 < 64; k4 += 4) {
            float4 av[4], bv[4];
#pragma unroll
            for (int r = 0; r < 4; r++) av[r] = *(const float4*)&Xs[i0 + r][k4];
#pragma unroll
            for (int c = 0; c < 4; c++) bv[c] = *(const float4*)&WsT[c0 + c][k4];
#pragma unroll
            for (int r = 0; r < 4; r++)
#pragma unroll
                for (int c = 0; c < 4; c++)
                    acc[r][c] += av[r].x * bv[c].x + av[r].y * bv[c].y +
                                 av[r].z * bv[c].z + av[r].w * bv[c].w;
        }
        __syncthreads();
    }

#pragma unroll
    for (int r = 0; r < 4; r++)
#pragma unroll
        for (int c = 0; c < 4; c++)
            outp[(size_t)(row0 + i0 + r) * HS + (c0 + c)] = acc[r][c];
}

// ---------------------------------------------------------------------------
// Flash attention with prefix-LM mask.
//   rows t < IL  : attend cols [0, IL)
//   rows t >= IL : attend cols [0, t]
// block = 64 query rows, 256 threads; KV tiles of 64.
// dynamic smem: Qs, Ks, Vs, Ps each 64x68 fp32.
// ---------------------------------------------------------------------------
extern __shared__ float dyn_smem[];

__global__ void attn_kernel(float* __restrict__ out) {
    float* Qs = dyn_smem;            // [64][68]
    float* Ks = Qs + 64 * 68;
    float* Vs = Ks + 64 * 68;
    float* Ps = Vs + 64 * 68;

    const int qb = (int)gridDim.x - 1 - (int)blockIdx.x;  // longest first
    const int b = blockIdx.y;
    const int tid = threadIdx.x;
    const int ty = tid >> 4, tx = tid & 15;
    const int i0 = ty * 4, c0 = tx * 4;

    const float* Q = g_q + (size_t)b * CL * HS;
    const float* K = g_k + (size_t)b * CL * HS;
    const float* V = g_v + (size_t)b * CL * HS;

    for (int i = tid; i < 4096; i += 256) {
        int r = i >> 6, k = i & 63;
        Qs[r * 68 + k] = Q[(size_t)(qb * 64 + r) * HS + k];
    }

    float m[4], l[4], o[4][4];
#pragma unroll
    for (int r = 0; r < 4; r++) {
        m[r] = -1e30f;
        l[r] = 0.f;
#pragma unroll
        for (int c = 0; c < 4; c++) o[r][c] = 0.f;
    }

    const float SCALE = 0.044194173824159216f;  // 512^-0.5
    const int kbEnd = (qb < IL / 64) ? (IL / 64) : (qb + 1);

    for (int kb = 0; kb < kbEnd; kb++) {
        __syncthreads();  // previous PV done; Ks/Vs/Ps free
        for (int i = tid; i < 4096; i += 256) {
            int r = i >> 6, k = i & 63;
            Ks[r * 68 + k] = K[(size_t)(kb * 64 + r) * HS + k];
            Vs[r * 68 + k] = V[(size_t)(kb * 64 + r) * HS + k];
        }
        __syncthreads();

        // S = Q K^T (4x4 micro-tile per thread)
        float s[4][4] = {};
#pragma unroll
        for (int k4 = 0; k4 < 64; k4 += 4) {
            float4 qv[4], kv[4];
#pragma unroll
            for (int r = 0; r < 4; r++) qv[r] = *(const float4*)&Qs[(i0 + r) * 68 + k4];
#pragma unroll
            for (int c = 0; c < 4; c++) kv[c] = *(const float4*)&Ks[(c0 + c) * 68 + k4];
#pragma unroll
            for (int r = 0; r < 4; r++)
#pragma unroll
                for (int c = 0; c < 4; c++)
                    s[r][c] += qv[r].x * kv[c].x + qv[r].y * kv[c].y +
                               qv[r].z * kv[c].z + qv[r].w * kv[c].w;
        }

        const bool diag = (kb == qb) && (qb >= IL / 64);
#pragma unroll
        for (int r = 0; r < 4; r++)
#pragma unroll
            for (int c = 0; c < 4; c++) {
                s[r][c] *= SCALE;
                if (diag && (c0 + c) > (i0 + r)) s[r][c] = -1e30f;
            }

        // online softmax per row (reduce across 16 lanes of same row group)
#pragma unroll
        for (int r = 0; r < 4; r++) {
            float rm = fmaxf(fmaxf(s[r][0], s[r][1]), fmaxf(s[r][2], s[r][3]));
#pragma unroll
            for (int d = 1; d < 16; d <<= 1)
                rm = fmaxf(rm, __shfl_xor_sync(0xffffffffu, rm, d));
            float mn = fmaxf(m[r], rm);
            float alpha = __expf(m[r] - mn);
            float sum = 0.f;
#pragma unroll
            for (int c = 0; c < 4; c++) {
                float p = __expf(s[r][c] - mn);
                s[r][c] = p;
                sum += p;
            }
#pragma unroll
            for (int d = 1; d < 16; d <<= 1)
                sum += __shfl_xor_sync(0xffffffffu, sum, d);
            l[r] = l[r] * alpha + sum;
            m[r] = mn;
#pragma unroll
            for (int c = 0; c < 4; c++) {
                o[r][c] *= alpha;
                Ps[(i0 + r) * 68 + (c0 + c)] = s[r][c];
            }
        }
        __syncthreads();

        // O += P @ V
#pragma unroll
        for (int j4 = 0; j4 < 64; j4 += 4) {
            float4 pv[4], vv[4];
#pragma unroll
            for (int r = 0; r < 4; r++) pv[r] = *(const float4*)&Ps[(i0 + r) * 68 + j4];
#pragma unroll
            for (int jj = 0; jj < 4; jj++) vv[jj] = *(const float4*)&Vs[(j4 + jj) * 68 + c0];
#pragma unroll
            for (int r = 0; r < 4; r++) {
                o[r][0] += pv[r].x * vv[0].x + pv[r].y * vv[1].x + pv[r].z * vv[2].x + pv[r].w * vv[3].x;
                o[r][1] += pv[r].x * vv[0].y + pv[r].y * vv[1].y + pv[r].z * vv[2].y + pv[r].w * vv[3].y;
                o[r][2] += pv[r].x * vv[0].z + pv[r].y * vv[1].z + pv[r].z * vv[2].z + pv[r].w * vv[3].z;
                o[r][3] += pv[r].x * vv[0].w + pv[r].y * vv[1].w + pv[r].z * vv[2].w + pv[r].w * vv[3].w;
            }
        }
    }

    // epilogue: normalize and store
#pragma unroll
    for (int r = 0; r < 4; r++) {
        float inv = 1.0f / l[r];
#pragma unroll
        for (int c = 0; c < 4; c++)
            out[((size_t)b * CL + qb * 64 + i0 + r) * HS + (c0 + c)] = o[r][c] * inv;
    }
}

extern "C" void kernel_launch(void* const* d_in, const int* in_sizes, int n_in,
                              void* d_out, int out_size) {
    const float* x  = (const float*)d_in[0];
    const float* Wq = (const float*)d_in[1];
    const float* Wk = (const float*)d_in[2];
    const float* Wv = (const float*)d_in[3];
    float* out = (float*)d_out;

    dim3 gproj(BATCHN * CL / 64, 3);
    proj_kernel<<<gproj, 256>>>(x, Wq, Wk, Wv);

    const int smem_bytes = 4 * 64 * 68 * (int)sizeof(float);  // 69632
    cudaFuncSetAttribute(attn_kernel, cudaFuncAttributeMaxDynamicSharedMemorySize,
                         smem_bytes);
    dim3 gattn(CL / 64, BATCHN);
    attn_kernel<<<gattn, 256, smem_bytes>>>(out);
}

// round 2
// speedup vs baseline: 2.9582x; 2.9582x over previous
#include <cuda_runtime.h>
#include <cstdint>

#define CL 4096
#define IL 1024
#define NE 512
#define HS 64
#define BATCHN 8

// fp32 scratch for projected q,k,v (values tf32-rounded at attn smem load)
__device__ float g_q[BATCHN * CL * HS];
__device__ float g_k[BATCHN * CL * HS];
__device__ float g_v[BATCHN * CL * HS];

__device__ __forceinline__ uint32_t to_tf32(float f) {
    uint32_t u;
    asm("cvt.rna.tf32.f32 %0, %1;" : "=r"(u) : "f"(f));
    return u;
}

__device__ __forceinline__ void mma_tf32(float c[4],
                                         uint32_t a0, uint32_t a1, uint32_t a2, uint32_t a3,
                                         uint32_t b0, uint32_t b1) {
    asm volatile(
        "mma.sync.aligned.m16n8k8.row.col.f32.tf32.tf32.f32 "
        "{%0,%1,%2,%3}, {%4,%5,%6,%7}, {%8,%9}, {%0,%1,%2,%3};\n"
        : "+f"(c[0]), "+f"(c[1]), "+f"(c[2]), "+f"(c[3])
        : "r"(a0), "r"(a1), "r"(a2), "r"(a3), "r"(b0), "r"(b1));
}

#define LDU(p) (*(const uint32_t*)(p))

// ---------------------------------------------------------------------------
// Projection via tf32 mma: out[64 rows x 64 cols] = X[64x512] @ W[512x64]
// 128 threads = 4 warps, warp w owns rows [16w,16w+16), all 64 cols (8 n-tiles)
// ---------------------------------------------------------------------------
__global__ __launch_bounds__(128) void proj_kernel(const float* __restrict__ x,
                                                   const float* __restrict__ Wq,
                                                   const float* __restrict__ Wk,
                                                   const float* __restrict__ Wv) {
    __shared__ __align__(16) float Xs[64 * 68];
    __shared__ __align__(16) float Ws[64 * 68];   // [k][n]

    const int mat = blockIdx.y;
    const float* W = (mat == 0) ? Wq : ((mat == 1) ? Wk : Wv);
    float* outp = (mat == 0) ? g_q : ((mat == 1) ? g_k : g_v);

    const int tid = threadIdx.x;
    const int lane = tid & 31, warp = tid >> 5;
    const int g = lane >> 2, tig = lane & 3;
    const int m0 = warp * 16;
    const int row0 = blockIdx.x * 64;

    float acc[8][4] = {};

    for (int kc = 0; kc < NE / 64; kc++) {
        for (int i = tid; i < 1024; i += 128) {
            int r = i >> 4, f = i & 15;
            float4 xv = ((const float4*)x)[(size_t)(row0 + r) * (NE / 4) + kc * 16 + f];
            float4 wv = ((const float4*)W)[(size_t)(kc * 64 + r) * (HS / 4) + f];
            float* xd = Xs + r * 68 + f * 4;
            float* wd = Ws + r * 68 + f * 4;
            xd[0] = __uint_as_float(to_tf32(xv.x)); xd[1] = __uint_as_float(to_tf32(xv.y));
            xd[2] = __uint_as_float(to_tf32(xv.z)); xd[3] = __uint_as_float(to_tf32(xv.w));
            wd[0] = __uint_as_float(to_tf32(wv.x)); wd[1] = __uint_as_float(to_tf32(wv.y));
            wd[2] = __uint_as_float(to_tf32(wv.z)); wd[3] = __uint_as_float(to_tf32(wv.w));
        }
        __syncthreads();
#pragma unroll
        for (int k0 = 0; k0 < 64; k0 += 8) {
            uint32_t a0 = LDU(&Xs[(m0 + g) * 68 + k0 + tig]);
            uint32_t a1 = LDU(&Xs[(m0 + g + 8) * 68 + k0 + tig]);
            uint32_t a2 = LDU(&Xs[(m0 + g) * 68 + k0 + tig + 4]);
            uint32_t a3 = LDU(&Xs[(m0 + g + 8) * 68 + k0 + tig + 4]);
#pragma unroll
            for (int nt = 0; nt < 8; nt++) {
                uint32_t b0 = LDU(&Ws[(k0 + tig) * 68 + nt * 8 + g]);
                uint32_t b1 = LDU(&Ws[(k0 + tig + 4) * 68 + nt * 8 + g]);
                mma_tf32(acc[nt], a0, a1, a2, a3, b0, b1);
            }
        }
        __syncthreads();
    }

    const int r0 = row0 + m0 + g, r1 = r0 + 8;
#pragma unroll
    for (int nt = 0; nt < 8; nt++) {
        int c = nt * 8 + 2 * tig;
        outp[(size_t)r0 * HS + c] = acc[nt][0];
        outp[(size_t)r0 * HS + c + 1] = acc[nt][1];
        outp[(size_t)r1 * HS + c] = acc[nt][2];
        outp[(size_t)r1 * HS + c + 1] = acc[nt][3];
    }
}

// ---------------------------------------------------------------------------
// Flash attention, prefix-LM mask, tf32 mma.
// CTA = 64 q rows, 128 threads / 4 warps; warp w: rows [16w,16w+16), n=64 full
// (softmax entirely intra-warp). KV tiles of 64.
// ---------------------------------------------------------------------------
extern __shared__ float dyn_smem[];

__global__ __launch_bounds__(128) void attn_kernel(float* __restrict__ out) {
    float* Qs = dyn_smem;             // [64][68] (pre-scaled, tf32-rounded)
    float* Ks = Qs + 64 * 68;
    float* Vs = Ks + 64 * 68;
    float* Ps = Vs + 64 * 68;

    const int qb = (int)gridDim.x - 1 - (int)blockIdx.x;   // longest first
    const int b = blockIdx.y;
    const int tid = threadIdx.x;
    const int lane = tid & 31, warp = tid >> 5;
    const int g = lane >> 2, tig = lane & 3;
    const int m0 = warp * 16;

    const float* Q = g_q + (size_t)b * CL * HS;
    const float* K = g_k + (size_t)b * CL * HS;
    const float* V = g_v + (size_t)b * CL * HS;

    const float SCALE = 0.044194173824159216f;   // 512^-0.5

    {
        const float4* Q4 = (const float4*)(Q + (size_t)qb * 64 * HS);
        for (int i = tid; i < 1024; i += 128) {
            int r = i >> 4, f = i & 15;
            float4 v = Q4[i];
            float* d = Qs + r * 68 + f * 4;
            d[0] = __uint_as_float(to_tf32(v.x * SCALE));
            d[1] = __uint_as_float(to_tf32(v.y * SCALE));
            d[2] = __uint_as_float(to_tf32(v.z * SCALE));
            d[3] = __uint_as_float(to_tf32(v.w * SCALE));
        }
    }

    float o[8][4] = {};
    float m[2] = {-1e30f, -1e30f};
    float l[2] = {0.f, 0.f};

    const int kbEnd = (qb < IL / 64) ? (IL / 64) : (qb + 1);

    for (int kb = 0; kb < kbEnd; kb++) {
        __syncthreads();   // prior PV done; Ks/Vs free
        {
            const float4* K4 = (const float4*)(K + (size_t)kb * 64 * HS);
            const float4* V4 = (const float4*)(V + (size_t)kb * 64 * HS);
            for (int i = tid; i < 1024; i += 128) {
                int r = i >> 4, f = i & 15;
                float4 kv = K4[i];
                float4 vv = V4[i];
                float* kd = Ks + r * 68 + f * 4;
                float* vd = Vs + r * 68 + f * 4;
                kd[0] = __uint_as_float(to_tf32(kv.x)); kd[1] = __uint_as_float(to_tf32(kv.y));
                kd[2] = __uint_as_float(to_tf32(kv.z)); kd[3] = __uint_as_float(to_tf32(kv.w));
                vd[0] = __uint_as_float(to_tf32(vv.x)); vd[1] = __uint_as_float(to_tf32(vv.y));
                vd[2] = __uint_as_float(to_tf32(vv.z)); vd[3] = __uint_as_float(to_tf32(vv.w));
            }
        }
        __syncthreads();

        // ---- S = Qs @ Ks^T  (warp stripe m16 x n64) ----
        float s[8][4] = {};
#pragma unroll
        for (int k0 = 0; k0 < 64; k0 += 8) {
            uint32_t a0 = LDU(&Qs[(m0 + g) * 68 + k0 + tig]);
            uint32_t a1 = LDU(&Qs[(m0 + g + 8) * 68 + k0 + tig]);
            uint32_t a2 = LDU(&Qs[(m0 + g) * 68 + k0 + tig + 4]);
            uint32_t a3 = LDU(&Qs[(m0 + g + 8) * 68 + k0 + tig + 4]);
#pragma unroll
            for (int nt = 0; nt < 8; nt++) {
                uint32_t b0 = LDU(&Ks[(nt * 8 + g) * 68 + k0 + tig]);
                uint32_t b1 = LDU(&Ks[(nt * 8 + g) * 68 + k0 + tig + 4]);
                mma_tf32(s[nt], a0, a1, a2, a3, b0, b1);
            }
        }

        // ---- mask (diagonal tile of causal region only) ----
        if (kb == qb && qb >= IL / 64) {
            const int r0 = m0 + g, r1 = r0 + 8;
#pragma unroll
            for (int nt = 0; nt < 8; nt++) {
                int c = nt * 8 + 2 * tig;
                if (c > r0)     s[nt][0] = -1e30f;
                if (c + 1 > r0) s[nt][1] = -1e30f;
                if (c > r1)     s[nt][2] = -1e30f;
                if (c + 1 > r1) s[nt][3] = -1e30f;
            }
        }

        // ---- online softmax (2 rows per thread, quad-reduce) ----
#pragma unroll
        for (int half = 0; half < 2; half++) {
            float rm = -1e30f;
#pragma unroll
            for (int nt = 0; nt < 8; nt++)
                rm = fmaxf(rm, fmaxf(s[nt][2 * half], s[nt][2 * half + 1]));
            rm = fmaxf(rm, __shfl_xor_sync(0xffffffffu, rm, 1));
            rm = fmaxf(rm, __shfl_xor_sync(0xffffffffu, rm, 2));
            float mn = fmaxf(m[half], rm);
            float alpha = __expf(m[half] - mn);
            m[half] = mn;
            float sum = 0.f;
            const int row = m0 + g + 8 * half;
#pragma unroll
            for (int nt = 0; nt < 8; nt++) {
                float p0 = __expf(s[nt][2 * half] - mn);
                float p1 = __expf(s[nt][2 * half + 1] - mn);
                sum += p0 + p1;
                int c = nt * 8 + 2 * tig;
                Ps[row * 68 + c] = __uint_as_float(to_tf32(p0));
                Ps[row * 68 + c + 1] = __uint_as_float(to_tf32(p1));
                o[nt][2 * half] *= alpha;
                o[nt][2 * half + 1] *= alpha;
            }
            sum += __shfl_xor_sync(0xffffffffu, sum, 1);
            sum += __shfl_xor_sync(0xffffffffu, sum, 2);
            l[half] = l[half] * alpha + sum;
        }
        __syncwarp();   // Ps rows for this warp written by this warp only

        // ---- O += Ps @ Vs ----
#pragma unroll
        for (int k0 = 0; k0 < 64; k0 += 8) {
            uint32_t a0 = LDU(&Ps[(m0 + g) * 68 + k0 + tig]);
            uint32_t a1 = LDU(&Ps[(m0 + g + 8) * 68 + k0 + tig]);
            uint32_t a2 = LDU(&Ps[(m0 + g) * 68 + k0 + tig + 4]);
            uint32_t a3 = LDU(&Ps[(m0 + g + 8) * 68 + k0 + tig + 4]);
#pragma unroll
            for (int nt = 0; nt < 8; nt++) {
                uint32_t b0 = LDU(&Vs[(k0 + tig) * 68 + nt * 8 + g]);
                uint32_t b1 = LDU(&Vs[(k0 + tig + 4) * 68 + nt * 8 + g]);
                mma_tf32(o[nt], a0, a1, a2, a3, b0, b1);
            }
        }
    }

    // ---- epilogue ----
    const float inv0 = 1.0f / l[0], inv1 = 1.0f / l[1];
    float* O = out + ((size_t)b * CL + qb * 64) * HS;
    const int r0 = m0 + g, r1 = r0 + 8;
#pragma unroll
    for (int nt = 0; nt < 8; nt++) {
        int c = nt * 8 + 2 * tig;
        O[(size_t)r0 * HS + c] = o[nt][0] * inv0;
        O[(size_t)r0 * HS + c + 1] = o[nt][1] * inv0;
        O[(size_t)r1 * HS + c] = o[nt][2] * inv1;
        O[(size_t)r1 * HS + c + 1] = o[nt][3] * inv1;
    }
}

extern "C" void kernel_launch(void* const* d_in, const int* in_sizes, int n_in,
                              void* d_out, int out_size) {
    const float* x  = (const float*)d_in[0];
    const float* Wq = (const float*)d_in[1];
    const float* Wk = (const float*)d_in[2];
    const float* Wv = (const float*)d_in[3];
    float* out = (float*)d_out;

    dim3 gproj(BATCHN * CL / 64, 3);
    proj_kernel<<<gproj, 128>>>(x, Wq, Wk, Wv);

    const int smem_bytes = 4 * 64 * 68 * (int)sizeof(float);   // 69632
    static bool attr_set = false;
    cudaFuncSetAttribute(attn_kernel, cudaFuncAttributeMaxDynamicSharedMemorySize,
                         smem_bytes);
    (void)attr_set;
    dim3 gattn(CL / 64, BATCHN);
    attn_kernel<<<gattn, 128, smem_bytes>>>(out);
}

// round 4
// speedup vs baseline: 7.0802x; 2.3934x over previous
#include <cuda_runtime.h>
#include <cuda_fp16.h>
#include <cstdint>

#define CL 4096
#define IL 1024
#define NE 512
#define HS 64
#define BATCHN 8

// half scratch; q pre-scaled by 512^-0.5 * log2(e)
__device__ __half g_q[BATCHN * CL * HS];
__device__ __half g_k[BATCHN * CL * HS];
__device__ __half g_v[BATCHN * CL * HS];

#define QSCALE 0.06375871654f  /* 512^-0.5 * log2(e) */

__device__ __forceinline__ uint32_t smem_u32(const void* p) {
    return (uint32_t)__cvta_generic_to_shared(p);
}
__device__ __forceinline__ uint32_t h2_as_u32(__half2 h) {
    return *reinterpret_cast<uint32_t*>(&h);
}
__device__ __forceinline__ void ldsm4(uint32_t& r0, uint32_t& r1, uint32_t& r2,
                                      uint32_t& r3, uint32_t a) {
    asm volatile("ldmatrix.sync.aligned.m8n8.x4.shared.b16 {%0,%1,%2,%3},[%4];\n"
                 : "=r"(r0), "=r"(r1), "=r"(r2), "=r"(r3) : "r"(a));
}
__device__ __forceinline__ void ldsm4t(uint32_t& r0, uint32_t& r1, uint32_t& r2,
                                       uint32_t& r3, uint32_t a) {
    asm volatile("ldmatrix.sync.aligned.m8n8.x4.trans.shared.b16 {%0,%1,%2,%3},[%4];\n"
                 : "=r"(r0), "=r"(r1), "=r"(r2), "=r"(r3) : "r"(a));
}
__device__ __forceinline__ void mma16816(float c[4], const uint32_t a[4],
                                         uint32_t b0, uint32_t b1) {
    asm volatile(
        "mma.sync.aligned.m16n8k16.row.col.f32.f16.f16.f32 "
        "{%0,%1,%2,%3},{%4,%5,%6,%7},{%8,%9},{%0,%1,%2,%3};\n"
        : "+f"(c[0]), "+f"(c[1]), "+f"(c[2]), "+f"(c[3])
        : "r"(a[0]), "r"(a[1]), "r"(a[2]), "r"(a[3]), "r"(b0), "r"(b1));
}
__device__ __forceinline__ void cp16(uint32_t dst, const void* src) {
    asm volatile("cp.async.cg.shared.global [%0],[%1],16;\n" ::"r"(dst), "l"(src));
}
__device__ __forceinline__ float ex2f(float x) {
    float y;
    asm("ex2.approx.f32 %0, %1;" : "=f"(y) : "f"(x));
    return y;
}

#define KST 72  // smem row stride in halves (144B: conflict-free for ldmatrix)

// ---------------------------------------------------------------------------
// Projection: fp16 mma. block = 64 rows, 128 thr / 4 warps; blockIdx.y = matrix.
// ---------------------------------------------------------------------------
__global__ __launch_bounds__(128) void proj_kernel(const float* __restrict__ x,
                                                   const float* __restrict__ Wq,
                                                   const float* __restrict__ Wk,
                                                   const float* __restrict__ Wv) {
    __shared__ __align__(16) __half Xs[64 * KST];
    __shared__ __align__(16) __half Ws[64 * KST];

    const int mat = blockIdx.y;
    const float* W = (mat == 0) ? Wq : ((mat == 1) ? Wk : Wv);
    __half* outp = (mat == 0) ? g_q : ((mat == 1) ? g_k : g_v);

    const int tid = threadIdx.x, lane = tid & 31, warp = tid >> 5;
    const int g = lane >> 2, tig = lane & 3;
    const int mm = lane >> 3, rr = lane & 7;
    const int m0 = warp * 16;
    const int row0 = blockIdx.x * 64;

    float acc[8][4] = {};

    for (int kc = 0; kc < NE / 64; kc++) {
#pragma unroll
        for (int i = 0; i < 8; i++) {
            int c = tid + i * 128;         // 0..1023 float4 chunks
            int r = c >> 4, f = c & 15;
            float4 xv = ((const float4*)x)[(size_t)(row0 + r) * (NE / 4) + kc * 16 + f];
            float4 wv = ((const float4*)W)[(size_t)(kc * 64 + r) * (HS / 4) + f];
            *(__half2*)(Xs + r * KST + f * 4)     = __floats2half2_rn(xv.x, xv.y);
            *(__half2*)(Xs + r * KST + f * 4 + 2) = __floats2half2_rn(xv.z, xv.w);
            *(__half2*)(Ws + r * KST + f * 4)     = __floats2half2_rn(wv.x, wv.y);
            *(__half2*)(Ws + r * KST + f * 4 + 2) = __floats2half2_rn(wv.z, wv.w);
        }
        __syncthreads();
        const uint32_t xb = smem_u32(Xs), wb = smem_u32(Ws);
#pragma unroll
        for (int ks = 0; ks < 4; ks++) {
            uint32_t a[4];
            ldsm4(a[0], a[1], a[2], a[3],
                  xb + ((m0 + (mm & 1) * 8 + rr) * KST + ks * 16 + (mm >> 1) * 8) * 2);
#pragma unroll
            for (int j = 0; j < 4; j++) {
                uint32_t b0, b1, b2, b3;
                ldsm4t(b0, b1, b2, b3,
                       wb + ((ks * 16 + (mm & 1) * 8 + rr) * KST + j * 16 + (mm >> 1) * 8) * 2);
                mma16816(acc[2 * j], a, b0, b1);
                mma16816(acc[2 * j + 1], a, b2, b3);
            }
        }
        __syncthreads();
    }

    const float sc = (mat == 0) ? QSCALE : 1.0f;
    const int r0 = row0 + m0 + g, r1 = r0 + 8;
#pragma unroll
    for (int nt = 0; nt < 8; nt++) {
        int c = nt * 8 + 2 * tig;
        *(__half2*)(outp + (size_t)r0 * HS + c) = __floats2half2_rn(acc[nt][0] * sc, acc[nt][1] * sc);
        *(__half2*)(outp + (size_t)r1 * HS + c) = __floats2half2_rn(acc[nt][2] * sc, acc[nt][3] * sc);
    }
}

// ---------------------------------------------------------------------------
// Flash attention, prefix-LM mask, fp16 mma, register-resident Q & P,
// cp.async double-buffered K/V.
// ---------------------------------------------------------------------------
extern __shared__ __half sm_attn[];

__global__ __launch_bounds__(128) void attn_kernel(float* __restrict__ out) {
    const int qb = (int)gridDim.x - 1 - (int)blockIdx.x;  // longest first
    const int b = blockIdx.y;
    const int tid = threadIdx.x, lane = tid & 31, warp = tid >> 5;
    const int g = lane >> 2, tig = lane & 3;
    const int mm = lane >> 3, rr = lane & 7;
    const int m0 = warp * 16;

    const __half* Q = g_q + (size_t)b * CL * HS + (size_t)qb * 64 * HS;
    const __half* K = g_k + (size_t)b * CL * HS;
    const __half* V = g_v + (size_t)b * CL * HS;

    __half* Ks[2] = {sm_attn, sm_attn + 2 * 64 * KST};
    __half* Vs[2] = {sm_attn + 64 * KST, sm_attn + 3 * 64 * KST};

    // ---- stage Q tile, hoist A-fragments to registers ----
    for (int i = tid; i < 512; i += 128) {
        int r = i >> 3, f = i & 7;
        *(uint4*)(Ks[0] + r * KST + f * 8) = *(const uint4*)(Q + r * HS + f * 8);
    }
    __syncthreads();
    uint32_t qa[4][4];
    {
        const uint32_t qbase = smem_u32(Ks[0]);
#pragma unroll
        for (int kc = 0; kc < 4; kc++)
            ldsm4(qa[kc][0], qa[kc][1], qa[kc][2], qa[kc][3],
                  qbase + ((m0 + (mm & 1) * 8 + rr) * KST + kc * 16 + (mm >> 1) * 8) * 2);
    }
    __syncthreads();

    const int kbEnd = (qb < IL / 64) ? (IL / 64) : (qb + 1);

    // ---- prefetch tiles 0,1 ----
#pragma unroll
    for (int pf = 0; pf < 2; pf++) {
        const __half* gk = K + (size_t)pf * 64 * HS;
        const __half* gv = V + (size_t)pf * 64 * HS;
#pragma unroll
        for (int i = 0; i < 4; i++) {
            int c = tid + i * 128, r = c >> 3, f = c & 7;
            cp16(smem_u32(Ks[pf] + r * KST + f * 8), gk + r * HS + f * 8);
            cp16(smem_u32(Vs[pf] + r * KST + f * 8), gv + r * HS + f * 8);
        }
        asm volatile("cp.async.commit_group;\n");
    }

    float o[8][4] = {};
    float m[2] = {-1e30f, -1e30f};
    float l[2] = {0.f, 0.f};

    for (int kb = 0; kb < kbEnd; kb++) {
        const int bi = kb & 1;
        if (kb + 1 < kbEnd) asm volatile("cp.async.wait_group 1;\n");
        else                asm volatile("cp.async.wait_group 0;\n");
        __syncthreads();

        // ---- S = Q K^T ----
        float s[8][4] = {};
        const uint32_t kbase = smem_u32(Ks[bi]);
#pragma unroll
        for (int kc = 0; kc < 4; kc++) {
#pragma unroll
            for (int j = 0; j < 4; j++) {
                uint32_t b0, b1, b2, b3;
                ldsm4(b0, b1, b2, b3,
                      kbase + ((16 * j + (mm >> 1) * 8 + rr) * KST + kc * 16 + (mm & 1) * 8) * 2);
                mma16816(s[2 * j], qa[kc], b0, b1);
                mma16816(s[2 * j + 1], qa[kc], b2, b3);
            }
        }

        // ---- mask diagonal tile (causal region only) ----
        if (kb == qb && qb >= IL / 64) {
            const int r0 = m0 + g, r1 = r0 + 8;
#pragma unroll
            for (int nt = 0; nt < 8; nt++) {
                int c = nt * 8 + 2 * tig;
                if (c > r0)     s[nt][0] = -1e30f;
                if (c + 1 > r0) s[nt][1] = -1e30f;
                if (c > r1)     s[nt][2] = -1e30f;
                if (c + 1 > r1) s[nt][3] = -1e30f;
            }
        }

        // ---- online softmax (log2 domain; quad reduce) ----
#pragma unroll
        for (int h = 0; h < 2; h++) {
            float rm = -1e30f;
#pragma unroll
            for (int nt = 0; nt < 8; nt++)
                rm = fmaxf(rm, fmaxf(s[nt][2 * h], s[nt][2 * h + 1]));
            rm = fmaxf(rm, __shfl_xor_sync(0xffffffffu, rm, 1));
            rm = fmaxf(rm, __shfl_xor_sync(0xffffffffu, rm, 2));
            float mn = fmaxf(m[h], rm);
            float alpha = ex2f(m[h] - mn);
            m[h] = mn;
            float sum = 0.f;
#pragma unroll
            for (int nt = 0; nt < 8; nt++) {
                float p0 = ex2f(s[nt][2 * h] - mn);
                float p1 = ex2f(s[nt][2 * h + 1] - mn);
                s[nt][2 * h] = p0;
                s[nt][2 * h + 1] = p1;
                sum += p0 + p1;
                o[nt][2 * h] *= alpha;
                o[nt][2 * h + 1] *= alpha;
            }
            sum += __shfl_xor_sync(0xffffffffu, sum, 1);
            sum += __shfl_xor_sync(0xffffffffu, sum, 2);
            l[h] = l[h] * alpha + sum;
        }

        // ---- pack P to fp16 A-fragments (register-only) ----
        uint32_t pa[4][4];
#pragma unroll
        for (int kc = 0; kc < 4; kc++) {
            pa[kc][0] = h2_as_u32(__floats2half2_rn(s[2 * kc][0], s[2 * kc][1]));
            pa[kc][1] = h2_as_u32(__floats2half2_rn(s[2 * kc][2], s[2 * kc][3]));
            pa[kc][2] = h2_as_u32(__floats2half2_rn(s[2 * kc + 1][0], s[2 * kc + 1][1]));
            pa[kc][3] = h2_as_u32(__floats2half2_rn(s[2 * kc + 1][2], s[2 * kc + 1][3]));
        }

        // ---- O += P V ----
        const uint32_t vbase = smem_u32(Vs[bi]);
#pragma unroll
        for (int kc = 0; kc < 4; kc++) {
#pragma unroll
            for (int j = 0; j < 4; j++) {
                uint32_t b0, b1, b2, b3;
                ldsm4t(b0, b1, b2, b3,
                       vbase + ((kc * 16 + (mm & 1) * 8 + rr) * KST + 16 * j + (mm >> 1) * 8) * 2);
                mma16816(o[2 * j], pa[kc], b0, b1);
                mma16816(o[2 * j + 1], pa[kc], b2, b3);
            }
        }
        __syncthreads();

        // ---- prefetch tile kb+2 into the buffer just freed ----
        if (kb + 2 < kbEnd) {
            const __half* gk = K + (size_t)(kb + 2) * 64 * HS;
            const __half* gv = V + (size_t)(kb + 2) * 64 * HS;
#pragma unroll
            for (int i = 0; i < 4; i++) {
                int c = tid + i * 128, r = c >> 3, f = c & 7;
                cp16(smem_u32(Ks[bi] + r * KST + f * 8), gk + r * HS + f * 8);
                cp16(smem_u32(Vs[bi] + r * KST + f * 8), gv + r * HS + f * 8);
            }
            asm volatile("cp.async.commit_group;\n");
        }
    }

    // ---- epilogue ----
    const float inv0 = 1.0f / l[0], inv1 = 1.0f / l[1];
    float* O = out + ((size_t)b * CL + qb * 64) * HS;
    const int r0 = m0 + g, r1 = r0 + 8;
#pragma unroll
    for (int nt = 0; nt < 8; nt++) {
        int c = nt * 8 + 2 * tig;
        O[(size_t)r0 * HS + c]     = o[nt][0] * inv0;
        O[(size_t)r0 * HS + c + 1] = o[nt][1] * inv0;
        O[(size_t)r1 * HS + c]     = o[nt][2] * inv1;
        O[(size_t)r1 * HS + c + 1] = o[nt][3] * inv1;
    }
}

extern "C" void kernel_launch(void* const* d_in, const int* in_sizes, int n_in,
                              void* d_out, int out_size) {
    const float* x  = (const float*)d_in[0];
    const float* Wq = (const float*)d_in[1];
    const float* Wk = (const float*)d_in[2];
    const float* Wv = (const float*)d_in[3];
    float* out = (float*)d_out;

    dim3 gproj(BATCHN * CL / 64, 3);
    proj_kernel<<<gproj, 128>>>(x, Wq, Wk, Wv);

    const int smem_bytes = 4 * 64 * KST * (int)sizeof(__half);  // 36864
    dim3 gattn(CL / 64, BATCHN);
    attn_kernel<<<gattn, 128, smem_bytes>>>(out);
}

// round 5
// speedup vs baseline: 12.2047x; 1.7238x over previous
#include <cuda_runtime.h>
#include <cuda_fp16.h>
#include <cstdint>

#define CL 4096
#define IL 1024
#define NE 512
#define HS 64
#define BATCHN 8

// half scratch; q pre-scaled by 512^-0.5 * log2(e)
__device__ __half g_q[BATCHN * CL * HS];
__device__ __half g_k[BATCHN * CL * HS];
__device__ __half g_v[BATCHN * CL * HS];

#define QSCALE 0.06375871654f  /* 512^-0.5 * log2(e) */

__device__ __forceinline__ uint32_t smem_u32(const void* p) {
    return (uint32_t)__cvta_generic_to_shared(p);
}
__device__ __forceinline__ uint32_t h2_as_u32(__half2 h) {
    return *reinterpret_cast<uint32_t*>(&h);
}
__device__ __forceinline__ uint32_t h2exp2u(uint32_t x) {
    uint32_t y;
    asm("ex2.approx.f16x2 %0,%1;" : "=r"(y) : "r"(x));
    return y;
}
__device__ __forceinline__ void ldsm4(uint32_t& r0, uint32_t& r1, uint32_t& r2,
                                      uint32_t& r3, uint32_t a) {
    asm volatile("ldmatrix.sync.aligned.m8n8.x4.shared.b16 {%0,%1,%2,%3},[%4];\n"
                 : "=r"(r0), "=r"(r1), "=r"(r2), "=r"(r3) : "r"(a));
}
__device__ __forceinline__ void ldsm4t(uint32_t& r0, uint32_t& r1, uint32_t& r2,
                                       uint32_t& r3, uint32_t a) {
    asm volatile("ldmatrix.sync.aligned.m8n8.x4.trans.shared.b16 {%0,%1,%2,%3},[%4];\n"
                 : "=r"(r0), "=r"(r1), "=r"(r2), "=r"(r3) : "r"(a));
}
__device__ __forceinline__ void mma16816(float c[4], const uint32_t a[4],
                                         uint32_t b0, uint32_t b1) {
    asm volatile(
        "mma.sync.aligned.m16n8k16.row.col.f32.f16.f16.f32 "
        "{%0,%1,%2,%3},{%4,%5,%6,%7},{%8,%9},{%0,%1,%2,%3};\n"
        : "+f"(c[0]), "+f"(c[1]), "+f"(c[2]), "+f"(c[3])
        : "r"(a[0]), "r"(a[1]), "r"(a[2]), "r"(a[3]), "r"(b0), "r"(b1));
}
__device__ __forceinline__ void cp16(uint32_t dst, const void* src) {
    asm volatile("cp.async.cg.shared.global [%0],[%1],16;\n" ::"r"(dst), "l"(src));
}
__device__ __forceinline__ float ex2f(float x) {
    float y;
    asm("ex2.approx.f32 %0, %1;" : "=f"(y) : "f"(x));
    return y;
}

#define KST 72  // smem row stride in halves (conflict-free ldmatrix)

// ---------------------------------------------------------------------------
// Fused projection: q,k,v for 64 rows in one pass over x.
// ---------------------------------------------------------------------------
__global__ __launch_bounds__(128) void proj_kernel(const float* __restrict__ x,
                                                   const float* __restrict__ Wq,
                                                   const float* __restrict__ Wk,
                                                   const float* __restrict__ Wv) {
    __shared__ __align__(16) __half Xs[64 * KST];
    __shared__ __align__(16) __half Ws[3][64 * KST];

    const float* Wp[3] = {Wq, Wk, Wv};

    const int tid = threadIdx.x, lane = tid & 31, warp = tid >> 5;
    const int g = lane >> 2, tig = lane & 3;
    const int mm = lane >> 3, rr = lane & 7;
    const int m0 = warp * 16;
    const int row0 = blockIdx.x * 64;

    float acc[3][8][4] = {};

    for (int kc = 0; kc < NE / 64; kc++) {
#pragma unroll
        for (int i = 0; i < 8; i++) {
            int c = tid + i * 128, r = c >> 4, f = c & 15;
            float4 xv = ((const float4*)x)[(size_t)(row0 + r) * (NE / 4) + kc * 16 + f];
            *(__half2*)(Xs + r * KST + f * 4)     = __floats2half2_rn(xv.x, xv.y);
            *(__half2*)(Xs + r * KST + f * 4 + 2) = __floats2half2_rn(xv.z, xv.w);
        }
#pragma unroll
        for (int mi = 0; mi < 3; mi++) {
            const float* W = Wp[mi];
#pragma unroll
            for (int i = 0; i < 8; i++) {
                int c = tid + i * 128, r = c >> 4, f = c & 15;
                float4 wv = ((const float4*)W)[(size_t)(kc * 64 + r) * (HS / 4) + f];
                *(__half2*)(Ws[mi] + r * KST + f * 4)     = __floats2half2_rn(wv.x, wv.y);
                *(__half2*)(Ws[mi] + r * KST + f * 4 + 2) = __floats2half2_rn(wv.z, wv.w);
            }
        }
        __syncthreads();
        const uint32_t xb = smem_u32(Xs);
#pragma unroll
        for (int ks = 0; ks < 4; ks++) {
            uint32_t a[4];
            ldsm4(a[0], a[1], a[2], a[3],
                  xb + ((m0 + (mm & 1) * 8 + rr) * KST + ks * 16 + (mm >> 1) * 8) * 2);
#pragma unroll
            for (int mi = 0; mi < 3; mi++) {
                const uint32_t wb = smem_u32(Ws[mi]);
#pragma unroll
                for (int j = 0; j < 4; j++) {
                    uint32_t b0, b1, b2, b3;
                    ldsm4t(b0, b1, b2, b3,
                           wb + ((ks * 16 + (mm & 1) * 8 + rr) * KST + j * 16 + (mm >> 1) * 8) * 2);
                    mma16816(acc[mi][2 * j], a, b0, b1);
                    mma16816(acc[mi][2 * j + 1], a, b2, b3);
                }
            }
        }
        __syncthreads();
    }

    const int r0 = row0 + m0 + g, r1 = r0 + 8;
#pragma unroll
    for (int mi = 0; mi < 3; mi++) {
        __half* outp = (mi == 0) ? g_q : ((mi == 1) ? g_k : g_v);
        const float sc = (mi == 0) ? QSCALE : 1.0f;
#pragma unroll
        for (int nt = 0; nt < 8; nt++) {
            int c = nt * 8 + 2 * tig;
            *(__half2*)(outp + (size_t)r0 * HS + c) =
                __floats2half2_rn(acc[mi][nt][0] * sc, acc[mi][nt][1] * sc);
            *(__half2*)(outp + (size_t)r1 * HS + c) =
                __floats2half2_rn(acc[mi][nt][2] * sc, acc[mi][nt][3] * sc);
        }
    }
}

// ---------------------------------------------------------------------------
// Flash attention, prefix-LM mask, fp16 mma. Software-pipelined:
// PV(i) interleaved with QK(i+1); fp16x2 exp; cp.async double buffer.
// ---------------------------------------------------------------------------
extern __shared__ __half sm_attn[];

__global__ __launch_bounds__(128) void attn_kernel(float* __restrict__ out) {
    const int qb = (int)gridDim.x - 1 - (int)blockIdx.x;  // longest first
    const int b = blockIdx.y;
    const int tid = threadIdx.x, lane = tid & 31, warp = tid >> 5;
    const int g = lane >> 2, tig = lane & 3;
    const int mm = lane >> 3, rr = lane & 7;
    const int m0 = warp * 16;

    const __half* Q = g_q + (size_t)b * CL * HS + (size_t)qb * 64 * HS;
    const __half* K = g_k + (size_t)b * CL * HS;
    const __half* V = g_v + (size_t)b * CL * HS;

    __half* Ks[2] = {sm_attn, sm_attn + 2 * 64 * KST};
    __half* Vs[2] = {sm_attn + 64 * KST, sm_attn + 3 * 64 * KST};

    // ---- stage Q tile, hoist A-fragments ----
    for (int i = tid; i < 512; i += 128) {
        int r = i >> 3, f = i & 7;
        *(uint4*)(Ks[0] + r * KST + f * 8) = *(const uint4*)(Q + r * HS + f * 8);
    }
    __syncthreads();
    uint32_t qa[4][4];
    {
        const uint32_t qbase = smem_u32(Ks[0]);
#pragma unroll
        for (int kc = 0; kc < 4; kc++)
            ldsm4(qa[kc][0], qa[kc][1], qa[kc][2], qa[kc][3],
                  qbase + ((m0 + (mm & 1) * 8 + rr) * KST + kc * 16 + (mm >> 1) * 8) * 2);
    }
    __syncthreads();

    const int kbEnd = (qb < IL / 64) ? (IL / 64) : (qb + 1);  // always >= 16

    // ---- prefetch tiles 0 and 1 (separate commit groups) ----
#pragma unroll
    for (int pf = 0; pf < 2; pf++) {
        const __half* gk = K + (size_t)pf * 64 * HS;
        const __half* gv = V + (size_t)pf * 64 * HS;
#pragma unroll
        for (int i = 0; i < 4; i++) {
            int c = tid + i * 128, r = c >> 3, f = c & 7;
            cp16(smem_u32(Ks[pf] + r * KST + f * 8), gk + r * HS + f * 8);
            cp16(smem_u32(Vs[pf] + r * KST + f * 8), gv + r * HS + f * 8);
        }
        asm volatile("cp.async.commit_group;\n");
    }

    float o[8][4] = {};
    float s[8][4] = {};
    float m[2] = {-1e30f, -1e30f};
    float l[2] = {0.f, 0.f};
    uint32_t pa[4][4];

    // ---- prologue: QK(0) (tile 0 never needs mask: qb>=16 && qb==0 impossible) ----
    asm volatile("cp.async.wait_group 1;\n");
    __syncthreads();
    {
        const uint32_t kbase = smem_u32(Ks[0]);
#pragma unroll
        for (int kc = 0; kc < 4; kc++)
#pragma unroll
            for (int j = 0; j < 4; j++) {
                uint32_t b0, b1, b2, b3;
                ldsm4(b0, b1, b2, b3,
                      kbase + ((16 * j + (mm >> 1) * 8 + rr) * KST + kc * 16 + (mm & 1) * 8) * 2);
                mma16816(s[2 * j], qa[kc], b0, b1);
                mma16816(s[2 * j + 1], qa[kc], b2, b3);
            }
    }

    for (int i = 0; i < kbEnd; i++) {
        const int bi = i & 1;

        // ---- online softmax on s(i); produce pa, update m,l, rescale o ----
#pragma unroll
        for (int h = 0; h < 2; h++) {
            float rm = -1e30f;
#pragma unroll
            for (int nt = 0; nt < 8; nt++)
                rm = fmaxf(rm, fmaxf(s[nt][2 * h], s[nt][2 * h + 1]));
            rm = fmaxf(rm, __shfl_xor_sync(0xffffffffu, rm, 1));
            rm = fmaxf(rm, __shfl_xor_sync(0xffffffffu, rm, 2));
            float mn = fmaxf(m[h], rm);
            float alpha = ex2f(m[h] - mn);
            m[h] = mn;
            float sum = 0.f;
#pragma unroll
            for (int nt = 0; nt < 8; nt++) {
                uint32_t p = h2exp2u(h2_as_u32(
                    __floats2half2_rn(s[nt][2 * h] - mn, s[nt][2 * h + 1] - mn)));
                pa[nt >> 1][(nt & 1) * 2 + h] = p;
                float2 f = __half22float2(*reinterpret_cast<__half2*>(&p));
                sum += f.x + f.y;
                o[nt][2 * h] *= alpha;
                o[nt][2 * h + 1] *= alpha;
            }
            sum += __shfl_xor_sync(0xffffffffu, sum, 1);
            sum += __shfl_xor_sync(0xffffffffu, sum, 2);
            l[h] = l[h] * alpha + sum;
        }

        if (i + 1 < kbEnd) {
            asm volatile("cp.async.wait_group 0;\n");  // tile i+1 landed
            __syncthreads();

            // ---- merged: O += P(i) V(i)  AND  s = Q K(i+1)^T ----
#pragma unroll
            for (int nt = 0; nt < 8; nt++)
#pragma unroll
                for (int e = 0; e < 4; e++) s[nt][e] = 0.f;

            const uint32_t vbase = smem_u32(Vs[bi]);
            const uint32_t kbase = smem_u32(Ks[bi ^ 1]);
#pragma unroll
            for (int kc = 0; kc < 4; kc++)
#pragma unroll
                for (int j = 0; j < 4; j++) {
                    uint32_t v0, v1, v2, v3, k0, k1, k2, k3;
                    ldsm4t(v0, v1, v2, v3,
                           vbase + ((kc * 16 + (mm & 1) * 8 + rr) * KST + 16 * j + (mm >> 1) * 8) * 2);
                    ldsm4(k0, k1, k2, k3,
                          kbase + ((16 * j + (mm >> 1) * 8 + rr) * KST + kc * 16 + (mm & 1) * 8) * 2);
                    mma16816(o[2 * j], pa[kc], v0, v1);
                    mma16816(o[2 * j + 1], pa[kc], v2, v3);
                    mma16816(s[2 * j], qa[kc], k0, k1);
                    mma16816(s[2 * j + 1], qa[kc], k2, k3);
                }

            // ---- mask diagonal tile (causal region only) ----
            if (i + 1 == qb && qb >= IL / 64) {
                const int r0 = m0 + g, r1 = r0 + 8;
#pragma unroll
                for (int nt = 0; nt < 8; nt++) {
                    int c = nt * 8 + 2 * tig;
                    if (c > r0)     s[nt][0] = -1e30f;
                    if (c + 1 > r0) s[nt][1] = -1e30f;
                    if (c > r1)     s[nt][2] = -1e30f;
                    if (c + 1 > r1) s[nt][3] = -1e30f;
                }
            }
            __syncthreads();  // all warps done reading buffer bi

            // ---- prefetch tile i+2 into freed buffer ----
            if (i + 2 < kbEnd) {
                const __half* gk = K + (size_t)(i + 2) * 64 * HS;
                const __half* gv = V + (size_t)(i + 2) * 64 * HS;
#pragma unroll
                for (int ii = 0; ii < 4; ii++) {
                    int c = tid + ii * 128, r = c >> 3, f = c & 7;
                    cp16(smem_u32(Ks[bi] + r * KST + f * 8), gk + r * HS + f * 8);
                    cp16(smem_u32(Vs[bi] + r * KST + f * 8), gv + r * HS + f * 8);
                }
                asm volatile("cp.async.commit_group;\n");
            }
        } else {
            // ---- last tile: PV only ----
            const uint32_t vbase = smem_u32(Vs[bi]);
#pragma unroll
            for (int kc = 0; kc < 4; kc++)
#pragma unroll
                for (int j = 0; j < 4; j++) {
                    uint32_t v0, v1, v2, v3;
                    ldsm4t(v0, v1, v2, v3,
                           vbase + ((kc * 16 + (mm & 1) * 8 + rr) * KST + 16 * j + (mm >> 1) * 8) * 2);
                    mma16816(o[2 * j], pa[kc], v0, v1);
                    mma16816(o[2 * j + 1], pa[kc], v2, v3);
                }
        }
    }

    // ---- epilogue ----
    const float inv0 = 1.0f / l[0], inv1 = 1.0f / l[1];
    float* O = out + ((size_t)b * CL + qb * 64) * HS;
    const int r0 = m0 + g, r1 = r0 + 8;
#pragma unroll
    for (int nt = 0; nt < 8; nt++) {
        int c = nt * 8 + 2 * tig;
        O[(size_t)r0 * HS + c]     = o[nt][0] * inv0;
        O[(size_t)r0 * HS + c + 1] = o[nt][1] * inv0;
        O[(size_t)r1 * HS + c]     = o[nt][2] * inv1;
        O[(size_t)r1 * HS + c + 1] = o[nt][3] * inv1;
    }
}

extern "C" void kernel_launch(void* const* d_in, const int* in_sizes, int n_in,
                              void* d_out, int out_size) {
    const float* x  = (const float*)d_in[0];
    const float* Wq = (const float*)d_in[1];
    const float* Wk = (const float*)d_in[2];
    const float* Wv = (const float*)d_in[3];
    float* out = (float*)d_out;

    proj_kernel<<<BATCHN * CL / 64, 128>>>(x, Wq, Wk, Wv);

    const int smem_bytes = 4 * 64 * KST * (int)sizeof(__half);  // 36864
    dim3 gattn(CL / 64, BATCHN);
    attn_kernel<<<gattn, 128, smem_bytes>>>(out);
}

// round 6
// speedup vs baseline: 12.2561x; 1.0042x over previous
#include <cuda_runtime.h>
#include <cuda_fp16.h>
#include <cstdint>

#define CL 4096
#define IL 1024
#define NE 512
#define HS 64
#define BATCHN 8

// half scratch; q pre-scaled by 512^-0.5 * log2(e)
__device__ __half g_q[BATCHN * CL * HS];
__device__ __half g_k[BATCHN * CL * HS];
__device__ __half g_v[BATCHN * CL * HS];

#define QSCALE 0.06375871654f  /* 512^-0.5 * log2(e) */

__device__ __forceinline__ uint32_t smem_u32(const void* p) {
    return (uint32_t)__cvta_generic_to_shared(p);
}
__device__ __forceinline__ uint32_t h2_as_u32(__half2 h) {
    return *reinterpret_cast<uint32_t*>(&h);
}
__device__ __forceinline__ uint32_t h2exp2u(uint32_t x) {
    uint32_t y;
    asm("ex2.approx.f16x2 %0,%1;" : "=r"(y) : "r"(x));
    return y;
}
__device__ __forceinline__ void ldsm4(uint32_t& r0, uint32_t& r1, uint32_t& r2,
                                      uint32_t& r3, uint32_t a) {
    asm volatile("ldmatrix.sync.aligned.m8n8.x4.shared.b16 {%0,%1,%2,%3},[%4];\n"
                 : "=r"(r0), "=r"(r1), "=r"(r2), "=r"(r3) : "r"(a));
}
__device__ __forceinline__ void ldsm4t(uint32_t& r0, uint32_t& r1, uint32_t& r2,
                                       uint32_t& r3, uint32_t a) {
    asm volatile("ldmatrix.sync.aligned.m8n8.x4.trans.shared.b16 {%0,%1,%2,%3},[%4];\n"
                 : "=r"(r0), "=r"(r1), "=r"(r2), "=r"(r3) : "r"(a));
}
__device__ __forceinline__ void mma16816(float c[4], const uint32_t a[4],
                                         uint32_t b0, uint32_t b1) {
    asm volatile(
        "mma.sync.aligned.m16n8k16.row.col.f32.f16.f16.f32 "
        "{%0,%1,%2,%3},{%4,%5,%6,%7},{%8,%9},{%0,%1,%2,%3};\n"
        : "+f"(c[0]), "+f"(c[1]), "+f"(c[2]), "+f"(c[3])
        : "r"(a[0]), "r"(a[1]), "r"(a[2]), "r"(a[3]), "r"(b0), "r"(b1));
}
__device__ __forceinline__ void cp16(uint32_t dst, const void* src) {
    asm volatile("cp.async.cg.shared.global [%0],[%1],16;\n" ::"r"(dst), "l"(src));
}
__device__ __forceinline__ float ex2f(float x) {
    float y;
    asm("ex2.approx.f32 %0, %1;" : "=f"(y) : "f"(x));
    return y;
}

#define KST 72  // smem row stride in halves (conflict-free ldmatrix)

// ---------------------------------------------------------------------------
// Fused projection: q,k,v for 64 rows in one pass over x.
// ---------------------------------------------------------------------------
__global__ __launch_bounds__(128) void proj_kernel(const float* __restrict__ x,
                                                   const float* __restrict__ Wq,
                                                   const float* __restrict__ Wk,
                                                   const float* __restrict__ Wv) {
    __shared__ __align__(16) __half Xs[64 * KST];
    __shared__ __align__(16) __half Ws[3][64 * KST];

    const float* Wp[3] = {Wq, Wk, Wv};

    const int tid = threadIdx.x, lane = tid & 31, warp = tid >> 5;
    const int g = lane >> 2, tig = lane & 3;
    const int mm = lane >> 3, rr = lane & 7;
    const int m0 = warp * 16;
    const int row0 = blockIdx.x * 64;

    float acc[3][8][4] = {};

    for (int kc = 0; kc < NE / 64; kc++) {
#pragma unroll
        for (int i = 0; i < 8; i++) {
            int c = tid + i * 128, r = c >> 4, f = c & 15;
            float4 xv = ((const float4*)x)[(size_t)(row0 + r) * (NE / 4) + kc * 16 + f];
            *(__half2*)(Xs + r * KST + f * 4)     = __floats2half2_rn(xv.x, xv.y);
            *(__half2*)(Xs + r * KST + f * 4 + 2) = __floats2half2_rn(xv.z, xv.w);
        }
#pragma unroll
        for (int mi = 0; mi < 3; mi++) {
            const float* W = Wp[mi];
#pragma unroll
            for (int i = 0; i < 8; i++) {
                int c = tid + i * 128, r = c >> 4, f = c & 15;
                float4 wv = ((const float4*)W)[(size_t)(kc * 64 + r) * (HS / 4) + f];
                *(__half2*)(Ws[mi] + r * KST + f * 4)     = __floats2half2_rn(wv.x, wv.y);
                *(__half2*)(Ws[mi] + r * KST + f * 4 + 2) = __floats2half2_rn(wv.z, wv.w);
            }
        }
        __syncthreads();
        const uint32_t xb = smem_u32(Xs);
#pragma unroll
        for (int ks = 0; ks < 4; ks++) {
            uint32_t a[4];
            ldsm4(a[0], a[1], a[2], a[3],
                  xb + ((m0 + (mm & 1) * 8 + rr) * KST + ks * 16 + (mm >> 1) * 8) * 2);
#pragma unroll
            for (int mi = 0; mi < 3; mi++) {
                const uint32_t wb = smem_u32(Ws[mi]);
#pragma unroll
                for (int j = 0; j < 4; j++) {
                    uint32_t b0, b1, b2, b3;
                    ldsm4t(b0, b1, b2, b3,
                           wb + ((ks * 16 + (mm & 1) * 8 + rr) * KST + j * 16 + (mm >> 1) * 8) * 2);
                    mma16816(acc[mi][2 * j], a, b0, b1);
                    mma16816(acc[mi][2 * j + 1], a, b2, b3);
                }
            }
        }
        __syncthreads();
    }

    const int r0 = row0 + m0 + g, r1 = r0 + 8;
#pragma unroll
    for (int mi = 0; mi < 3; mi++) {
        __half* outp = (mi == 0) ? g_q : ((mi == 1) ? g_k : g_v);
        const float sc = (mi == 0) ? QSCALE : 1.0f;
#pragma unroll
        for (int nt = 0; nt < 8; nt++) {
            int c = nt * 8 + 2 * tig;
            *(__half2*)(outp + (size_t)r0 * HS + c) =
                __floats2half2_rn(acc[mi][nt][0] * sc, acc[mi][nt][1] * sc);
            *(__half2*)(outp + (size_t)r1 * HS + c) =
                __floats2half2_rn(acc[mi][nt][2] * sc, acc[mi][nt][3] * sc);
        }
    }
}

// ---------------------------------------------------------------------------
// Flash attention, prefix-LM mask, fp16 mma. Software-pipelined:
// PV(i) interleaved with QK(i+1); fp16x2 exp; cp.async double buffer.
// ---------------------------------------------------------------------------
extern __shared__ __half sm_attn[];

__global__ __launch_bounds__(128) void attn_kernel(float* __restrict__ out) {
    const int qb = (int)gridDim.x - 1 - (int)blockIdx.x;  // longest first
    const int b = blockIdx.y;
    const int tid = threadIdx.x, lane = tid & 31, warp = tid >> 5;
    const int g = lane >> 2, tig = lane & 3;
    const int mm = lane >> 3, rr = lane & 7;
    const int m0 = warp * 16;

    const __half* Q = g_q + (size_t)b * CL * HS + (size_t)qb * 64 * HS;
    const __half* K = g_k + (size_t)b * CL * HS;
    const __half* V = g_v + (size_t)b * CL * HS;

    __half* Ks[2] = {sm_attn, sm_attn + 2 * 64 * KST};
    __half* Vs[2] = {sm_attn + 64 * KST, sm_attn + 3 * 64 * KST};

    // ---- stage Q tile, hoist A-fragments ----
    for (int i = tid; i < 512; i += 128) {
        int r = i >> 3, f = i & 7;
        *(uint4*)(Ks[0] + r * KST + f * 8) = *(const uint4*)(Q + r * HS + f * 8);
    }
    __syncthreads();
    uint32_t qa[4][4];
    {
        const uint32_t qbase = smem_u32(Ks[0]);
#pragma unroll
        for (int kc = 0; kc < 4; kc++)
            ldsm4(qa[kc][0], qa[kc][1], qa[kc][2], qa[kc][3],
                  qbase + ((m0 + (mm & 1) * 8 + rr) * KST + kc * 16 + (mm >> 1) * 8) * 2);
    }
    __syncthreads();

    const int kbEnd = (qb < IL / 64) ? (IL / 64) : (qb + 1);  // always >= 16

    // ---- prefetch tiles 0 and 1 (separate commit groups) ----
#pragma unroll
    for (int pf = 0; pf < 2; pf++) {
        const __half* gk = K + (size_t)pf * 64 * HS;
        const __half* gv = V + (size_t)pf * 64 * HS;
#pragma unroll
        for (int i = 0; i < 4; i++) {
            int c = tid + i * 128, r = c >> 3, f = c & 7;
            cp16(smem_u32(Ks[pf] + r * KST + f * 8), gk + r * HS + f * 8);
            cp16(smem_u32(Vs[pf] + r * KST + f * 8), gv + r * HS + f * 8);
        }
        asm volatile("cp.async.commit_group;\n");
    }

    float o[8][4] = {};
    float s[8][4] = {};
    float m[2] = {-1e30f, -1e30f};
    float l[2] = {0.f, 0.f};
    uint32_t pa[4][4];

    // ---- prologue: QK(0) (tile 0 never needs mask: qb>=16 && qb==0 impossible) ----
    asm volatile("cp.async.wait_group 1;\n");
    __syncthreads();
    {
        const uint32_t kbase = smem_u32(Ks[0]);
#pragma unroll
        for (int kc = 0; kc < 4; kc++)
#pragma unroll
            for (int j = 0; j < 4; j++) {
                uint32_t b0, b1, b2, b3;
                ldsm4(b0, b1, b2, b3,
                      kbase + ((16 * j + (mm >> 1) * 8 + rr) * KST + kc * 16 + (mm & 1) * 8) * 2);
                mma16816(s[2 * j], qa[kc], b0, b1);
                mma16816(s[2 * j + 1], qa[kc], b2, b3);
            }
    }

    for (int i = 0; i < kbEnd; i++) {
        const int bi = i & 1;

        // ---- online softmax on s(i); produce pa, update m,l, rescale o ----
#pragma unroll
        for (int h = 0; h < 2; h++) {
            float rm = -1e30f;
#pragma unroll
            for (int nt = 0; nt < 8; nt++)
                rm = fmaxf(rm, fmaxf(s[nt][2 * h], s[nt][2 * h + 1]));
            rm = fmaxf(rm, __shfl_xor_sync(0xffffffffu, rm, 1));
            rm = fmaxf(rm, __shfl_xor_sync(0xffffffffu, rm, 2));
            float mn = fmaxf(m[h], rm);
            float alpha = ex2f(m[h] - mn);
            m[h] = mn;
            float sum = 0.f;
#pragma unroll
            for (int nt = 0; nt < 8; nt++) {
                uint32_t p = h2exp2u(h2_as_u32(
                    __floats2half2_rn(s[nt][2 * h] - mn, s[nt][2 * h + 1] - mn)));
                pa[nt >> 1][(nt & 1) * 2 + h] = p;
                float2 f = __half22float2(*reinterpret_cast<__half2*>(&p));
                sum += f.x + f.y;
                o[nt][2 * h] *= alpha;
                o[nt][2 * h + 1] *= alpha;
            }
            sum += __shfl_xor_sync(0xffffffffu, sum, 1);
            sum += __shfl_xor_sync(0xffffffffu, sum, 2);
            l[h] = l[h] * alpha + sum;
        }

        if (i + 1 < kbEnd) {
            asm volatile("cp.async.wait_group 0;\n");  // tile i+1 landed
            __syncthreads();

            // ---- merged: O += P(i) V(i)  AND  s = Q K(i+1)^T ----
#pragma unroll
            for (int nt = 0; nt < 8; nt++)
#pragma unroll
                for (int e = 0; e < 4; e++) s[nt][e] = 0.f;

            const uint32_t vbase = smem_u32(Vs[bi]);
            const uint32_t kbase = smem_u32(Ks[bi ^ 1]);
#pragma unroll
            for (int kc = 0; kc < 4; kc++)
#pragma unroll
                for (int j = 0; j < 4; j++) {
                    uint32_t v0, v1, v2, v3, k0, k1, k2, k3;
                    ldsm4t(v0, v1, v2, v3,
                           vbase + ((kc * 16 + (mm & 1) * 8 + rr) * KST + 16 * j + (mm >> 1) * 8) * 2);
                    ldsm4(k0, k1, k2, k3,
                          kbase + ((16 * j + (mm >> 1) * 8 + rr) * KST + kc * 16 + (mm & 1) * 8) * 2);
                    mma16816(o[2 * j], pa[kc], v0, v1);
                    mma16816(o[2 * j + 1], pa[kc], v2, v3);
                    mma16816(s[2 * j], qa[kc], k0, k1);
                    mma16816(s[2 * j + 1], qa[kc], k2, k3);
                }

            // ---- mask diagonal tile (causal region only) ----
            if (i + 1 == qb && qb >= IL / 64) {
                const int r0 = m0 + g, r1 = r0 + 8;
#pragma unroll
                for (int nt = 0; nt < 8; nt++) {
                    int c = nt * 8 + 2 * tig;
                    if (c > r0)     s[nt][0] = -1e30f;
                    if (c + 1 > r0) s[nt][1] = -1e30f;
                    if (c > r1)     s[nt][2] = -1e30f;
                    if (c + 1 > r1) s[nt][3] = -1e30f;
                }
            }
            __syncthreads();  // all warps done reading buffer bi

            // ---- prefetch tile i+2 into freed buffer ----
            if (i + 2 < kbEnd) {
                const __half* gk = K + (size_t)(i + 2) * 64 * HS;
                const __half* gv = V + (size_t)(i + 2) * 64 * HS;
#pragma unroll
                for (int ii = 0; ii < 4; ii++) {
                    int c = tid + ii * 128, r = c >> 3, f = c & 7;
                    cp16(smem_u32(Ks[bi] + r * KST + f * 8), gk + r * HS + f * 8);
                    cp16(smem_u32(Vs[bi] + r * KST + f * 8), gv + r * HS + f * 8);
                }
                asm volatile("cp.async.commit_group;\n");
            }
        } else {
            // ---- last tile: PV only ----
            const uint32_t vbase = smem_u32(Vs[bi]);
#pragma unroll
            for (int kc = 0; kc < 4; kc++)
#pragma unroll
                for (int j = 0; j < 4; j++) {
                    uint32_t v0, v1, v2, v3;
                    ldsm4t(v0, v1, v2, v3,
                           vbase + ((kc * 16 + (mm & 1) * 8 + rr) * KST + 16 * j + (mm >> 1) * 8) * 2);
                    mma16816(o[2 * j], pa[kc], v0, v1);
                    mma16816(o[2 * j + 1], pa[kc], v2, v3);
                }
        }
    }

    // ---- epilogue ----
    const float inv0 = 1.0f / l[0], inv1 = 1.0f / l[1];
    float* O = out + ((size_t)b * CL + qb * 64) * HS;
    const int r0 = m0 + g, r1 = r0 + 8;
#pragma unroll
    for (int nt = 0; nt < 8; nt++) {
        int c = nt * 8 + 2 * tig;
        O[(size_t)r0 * HS + c]     = o[nt][0] * inv0;
        O[(size_t)r0 * HS + c + 1] = o[nt][1] * inv0;
        O[(size_t)r1 * HS + c]     = o[nt][2] * inv1;
        O[(size_t)r1 * HS + c + 1] = o[nt][3] * inv1;
    }
}

extern "C" void kernel_launch(void* const* d_in, const int* in_sizes, int n_in,
                              void* d_out, int out_size) {
    const float* x  = (const float*)d_in[0];
    const float* Wq = (const float*)d_in[1];
    const float* Wk = (const float*)d_in[2];
    const float* Wv = (const float*)d_in[3];
    float* out = (float*)d_out;

    proj_kernel<<<BATCHN * CL / 64, 128>>>(x, Wq, Wk, Wv);

    const int smem_bytes = 4 * 64 * KST * (int)sizeof(__half);  // 36864
    dim3 gattn(CL / 64, BATCHN);
    attn_kernel<<<gattn, 128, smem_bytes>>>(out);
}